// round 2
// baseline (speedup 1.0000x reference)
#include <cuda_runtime.h>
#include <cuda_bf16.h>

// Balloon-Windkessel BOLD, explicit Euler, 1000 steps. Strictly serial
// recurrence -> single-thread latency-optimized loop. MUFU EX2/LG2 emitted
// via inline PTX so we get the approx hardware ops regardless of nvcc flags.

#define N_STEPS 1000
#define DT      0.01f
#define ALPHA   0.32f
#define RHO     0.34f
#define V0      0.02f
#define K1      (7.0f * RHO)          // 2.38
#define K2      2.0f
#define K3      (2.0f * RHO - 0.2f)   // 0.48

__device__ __forceinline__ float ex2_approx(float x) {
    float r;
    asm("ex2.approx.f32 %0, %1;" : "=f"(r) : "f"(x));
    return r;
}
__device__ __forceinline__ float lg2_approx(float x) {
    float r;
    asm("lg2.approx.f32 %0, %1;" : "=f"(r) : "f"(x));
    return r;
}
__device__ __forceinline__ float rcp_approx(float x) {
    float r;
    asm("rcp.approx.f32 %0, %1;" : "=f"(r) : "f"(x));
    return r;
}

__global__ void __launch_bounds__(32, 1)
bold_euler_kernel(const float* __restrict__ mtt_ptr, float* __restrict__ y_out) {
    if (threadIdx.x != 0) return;

    const float mtt      = mtt_ptr[0];
    const float dt_mtt   = DT / mtt;           // precise divide, once
    const float inv_a    = 1.0f / ALPHA;       // 3.125
    const float inv_a_m1 = inv_a - 1.0f;       // 2.125
    const float inv_rho  = 1.0f / RHO;
    const float L66      = -0.5994621118f;     // log2(1 - RHO) = log2(0.66)

    float s = 0.0f;
    float f = 1.0f;
    float v = 1.0f;
    float q = 1.0f;

    #pragma unroll 4
    for (int t = 0; t < N_STEPS; ++t) {
        // --- shared log2(v): feeds v^(1/a) and v^(1/a - 1) -----------------
        float lv      = lg2_approx(v);
        float v_pow   = ex2_approx(inv_a * lv);      // v^(1/alpha)
        float vp_ov_v = ex2_approx(inv_a_m1 * lv);   // v^(1/alpha - 1)

        // --- oxygen extraction: E = 1 - 0.66^(1/f) -------------------------
        float E = 1.0f - ex2_approx(L66 * rcp_approx(f));

        // --- Euler updates (all derivatives from OLD state) ----------------
        // ds = u - kappa*s - gamma*(f-1)  with u=1, kappa=gamma=1
        float ds = 2.0f - s - f;
        float df = s;
        float dv = (f - v_pow) * dt_mtt;                       // includes DT
        float dq = (f * E * inv_rho - vp_ov_v * q) * dt_mtt;   // includes DT

        s = fmaf(DT, ds, s);
        f = fmaf(DT, df, f);
        float v_new = v + dv;
        float q_new = q + dq;

        // --- BOLD readout with NEW q, v ------------------------------------
        float inv_v = rcp_approx(v_new);         // off the v critical path
        float yt = V0 * (K1 * (1.0f - q_new)
                       + K2 * (1.0f - q_new * inv_v)
                       + K3 * (1.0f - v_new));
        y_out[t] = yt;

        v = v_new;
        q = q_new;
    }
}

extern "C" void kernel_launch(void* const* d_in, const int* in_sizes, int n_in,
                              void* d_out, int out_size) {
    const float* mtt = (const float*)d_in[0];
    float* y = (float*)d_out;
    bold_euler_kernel<<<1, 32>>>(mtt, y);
}

// round 3
// speedup vs baseline: 2.1542x; 2.1542x over previous
#include <cuda_runtime.h>
#include <cuda_bf16.h>

// Balloon-Windkessel BOLD, explicit Euler, 1000 steps.
// Phase 1 (parallel, 128 threads): (s,f) subsystem is LINEAR and independent
//   of (v,q); f_t has a closed form  f_t = 2 - r^t (cos(t*th) + sin(t*th)/sqrt3).
//   Precompute per-step coefficients a_t = f_t*dt/mtt, g_t = dt/mtt*f_t*E_t/rho
//   into shared memory (E_t = 1 - 0.66^(1/f_t)).
// Phase 2 (serial, 1 thread): (v,q) recurrence with NO MUFU on the critical
//   path: carry p = dtm*v^3.125, w = dtm*v^2.125, rv = 1/v, updated
//   multiplicatively via 3rd-order binomial series in x = dv/v (|x|<=0.01).

#define N_STEPS 1000
#define DT      0.01f
#define RHO     0.34f
#define V0      0.02f

// discrete closed-form constants for the linear (s,f) subsystem (h = 0.01)
#define LOG2R   (-0.0071769220f)   // log2(sqrt(1 - h + h^2))
#define THETA   (0.0087035531f)    // atan2(sqrt(3)/2*h, 1 - h/2)
#define INVSQ3  (0.57735026919f)
#define L66     (-0.5994621118f)   // log2(0.66)

// binomial series coefficients
#define P1 3.125f
#define P2 3.3203125f      // 3.125*2.125/2
#define P3 1.2451171875f   // 3.125*2.125*1.125/6
#define W1 2.125f
#define W2c 1.1953125f     // 2.125*1.125/2
#define W3 0.0498046875f   // 2.125*1.125*0.125/6

// BOLD readout constants: y = C - V0K1*q - V0K2*q/v - V0K3*v
#define YC   0.0972f   // V0*(K1+K2+K3) = 0.02*4.86
#define YK1  0.0476f   // V0*7*rho
#define YK2  0.04f     // V0*2
#define YK3  0.0096f   // V0*(2*rho-0.2)

__device__ __forceinline__ float ex2a(float x){ float r; asm("ex2.approx.f32 %0,%1;":"=f"(r):"f"(x)); return r; }
__device__ __forceinline__ float sina(float x){ float r; asm("sin.approx.f32 %0,%1;":"=f"(r):"f"(x)); return r; }
__device__ __forceinline__ float cosa(float x){ float r; asm("cos.approx.f32 %0,%1;":"=f"(r):"f"(x)); return r; }
__device__ __forceinline__ float rcpa(float x){ float r; asm("rcp.approx.f32 %0,%1;":"=f"(r):"f"(x)); return r; }

__global__ void __launch_bounds__(128, 1)
bold_euler_kernel(const float* __restrict__ mtt_ptr, float* __restrict__ y_out) {
    __shared__ float2 ag[N_STEPS];   // {a_t, g_t}

    const float mtt = mtt_ptr[0];
    const float dtm = DT / mtt;
    const float g_scale = dtm / RHO;

    // ---------------- Phase 1: parallel precompute of f_t, E_t -------------
    for (int t = threadIdx.x; t < N_STEPS; t += 128) {
        float tf  = (float)t;
        float rp  = ex2a(LOG2R * tf);          // r^t
        float ang = THETA * tf;
        float c   = cosa(ang);
        float s   = sina(ang);
        float f   = 2.0f - rp * fmaf(s, INVSQ3, c);
        float E   = 1.0f - ex2a(L66 * rcpa(f));
        ag[t] = make_float2(dtm * f, g_scale * f * E);
    }
    __syncthreads();

    if (threadIdx.x != 0) return;

    // ---------------- Phase 2: serial (v,q) loop, FMA-only -----------------
    float v  = 1.0f;
    float q  = 1.0f;
    float p  = dtm;    // dtm * v^3.125
    float w  = dtm;    // dtm * v^2.125
    float rv = 1.0f;   // 1 / v

    #pragma unroll 8
    for (int t = 0; t < N_STEPS; ++t) {
        float2 c2 = ag[t];
        float a_t = c2.x, g_t = c2.y;

        // q update uses OLD w, q
        float qn = fmaf(-w, q, q + g_t);

        // v update and series variable x = dv / v
        float dv = a_t - p;
        float vn = v + dv;
        float x  = dv * rv;
        float x2 = x * x;

        // 3rd-order binomial updates (Estrin)
        float Pp = fmaf(x2, fmaf(P3, x, P2),  fmaf(P1, x, 1.0f));
        float Ww = fmaf(x2, fmaf(W3, x, W2c), fmaf(W1, x, 1.0f));
        float Rr = fmaf(x2, 1.0f - x,         1.0f - x);        // 1 - x + x^2 - x^3
        float pn  = p  * Pp;
        float wn  = w  * Ww;
        float rvn = rv * Rr;

        // BOLD readout with NEW q, v
        float yt = fmaf(-YK1, qn, YC);
        yt = fmaf(-YK3, vn, yt);
        yt = fmaf(-YK2, qn * rvn, yt);
        y_out[t] = yt;

        v = vn; q = qn; p = pn; w = wn; rv = rvn;
    }
}

extern "C" void kernel_launch(void* const* d_in, const int* in_sizes, int n_in,
                              void* d_out, int out_size) {
    const float* mtt = (const float*)d_in[0];
    float* y = (float*)d_out;
    bold_euler_kernel<<<1, 128>>>(mtt, y);
}

// round 5
// speedup vs baseline: 6.4857x; 3.0107x over previous
#include <cuda_runtime.h>
#include <cuda_bf16.h>

// Balloon-Windkessel BOLD, explicit Euler, 1000 steps — PARALLEL-IN-TIME.
//
// (s,f): linear subsystem -> closed form per step (elementwise).
// v:     nonlinear scalar recurrence v_{k+1} = v_k + a_k - dtm*v_k^3.125.
//        Newton-linearize around guess -> affine recurrence -> parallel
//        affine scan; 5 Newton sweeps converge to the exact Euler trajectory.
// q:     linear given v -> one exact affine scan.
// y:     elementwise readout.
// One block, 1024 threads, thread t owns step t.

#define N_STEPS 1000
#define NT      1024
#define DT      0.01f
#define RHO     0.34f
#define NEWTON_ITERS 5

// closed-form constants for the linear (s,f) subsystem (h = 0.01)
#define LOG2R   (-0.0071769220f)   // log2(sqrt(1 - h + h^2))
#define THETA   (0.0087035531f)    // atan2(sqrt(3)/2*h, 1 - h/2)
#define INVSQ3  (0.57735026919f)
#define L66     (-0.5994621118f)   // log2(0.66)

// BOLD readout: y = YC - YK1*q - YK2*q/v - YK3*v
#define YC   0.0972f
#define YK1  0.0476f
#define YK2  0.04f
#define YK3  0.0096f

__device__ __forceinline__ float ex2a(float x){ float r; asm("ex2.approx.f32 %0,%1;":"=f"(r):"f"(x)); return r; }
__device__ __forceinline__ float lg2a(float x){ float r; asm("lg2.approx.f32 %0,%1;":"=f"(r):"f"(x)); return r; }
__device__ __forceinline__ float sina(float x){ float r; asm("sin.approx.f32 %0,%1;":"=f"(r):"f"(x)); return r; }
__device__ __forceinline__ float cosa(float x){ float r; asm("cos.approx.f32 %0,%1;":"=f"(r):"f"(x)); return r; }
__device__ __forceinline__ float rcpa(float x){ float r; asm("rcp.approx.f32 %0,%1;":"=f"(r):"f"(x)); return r; }

// Inclusive scan of affine maps x -> A*x + B over thread index.
// compose(later, earlier) = (A_l*A_e, A_l*B_e + B_l).
__device__ __forceinline__ void affine_scan(float& A, float& B,
                                            int lane, int warp,
                                            float* shA, float* shB) {
    __syncthreads();   // protect shA/shB reuse across calls
    #pragma unroll
    for (int d = 1; d < 32; d <<= 1) {
        float pA = __shfl_up_sync(0xffffffffu, A, d);
        float pB = __shfl_up_sync(0xffffffffu, B, d);
        if (lane >= d) { B = fmaf(A, pB, B); A = A * pA; }
    }
    if (lane == 31) { shA[warp] = A; shB[warp] = B; }
    __syncthreads();
    if (warp == 0) {
        float wA = shA[lane], wB = shB[lane];
        #pragma unroll
        for (int d = 1; d < 32; d <<= 1) {
            float pA = __shfl_up_sync(0xffffffffu, wA, d);
            float pB = __shfl_up_sync(0xffffffffu, wB, d);
            if (lane >= d) { wB = fmaf(wA, pB, wB); wA = wA * pA; }
        }
        shA[lane] = wA; shB[lane] = wB;
    }
    __syncthreads();
    if (warp > 0) {
        float wA = shA[warp - 1], wB = shB[warp - 1];  // prefix applies first
        B = fmaf(A, wB, B);
        A = A * wA;
    }
}

__global__ void __launch_bounds__(NT, 1)
bold_pits_kernel(const float* __restrict__ mtt_ptr, float* __restrict__ y_out) {
    __shared__ float shA[32], shB[32];
    __shared__ float shv[NT + 1];

    const int t    = threadIdx.x;
    const int lane = t & 31;
    const int warp = t >> 5;
    const bool active = (t < N_STEPS);

    const float mtt = mtt_ptr[0];
    const float dtm = DT / mtt;

    // ---- elementwise: f_t (closed form), E_t, per-step coefficients -------
    float a_t = 0.0f, g_t = 0.0f;
    if (active) {
        float tf  = (float)t;
        float rp  = ex2a(LOG2R * tf);
        float ang = THETA * tf;
        float f   = 2.0f - rp * fmaf(sina(ang), INVSQ3, cosa(ang));
        float E   = 1.0f - ex2a(L66 * rcpa(f));
        a_t = dtm * f;
        g_t = (dtm / RHO) * f * E;
    }

    // ---- Newton + affine scans for v --------------------------------------
    float vk = 1.0f;        // guess of v_t (state BEFORE step t)
    float v_next = 1.0f;    // v_{t+1}

    #pragma unroll 1
    for (int it = 0; it < NEWTON_ITERS; ++it) {
        float A = 1.0f, B = 0.0f;
        if (active) {
            float u = ex2a(2.125f * lg2a(vk));   // vk^2.125
            float P = dtm * vk * u;              // dtm * vk^3.125
            A = fmaf(-3.125f * dtm, u, 1.0f);
            B = fmaf(2.125f, P, a_t);
        }
        affine_scan(A, B, lane, warp, shA, shB);
        v_next = A + B;                          // v_{t+1} (v_0 = 1)

        // shift: thread t needs v_t for the next linearization
        shv[t + 1] = v_next;
        if (t == 0) shv[0] = 1.0f;
        __syncthreads();
        vk = shv[t];
    }

    // ---- exact affine scan for q ------------------------------------------
    float Aq = 1.0f, Bq = 0.0f;
    if (active) {
        float u = ex2a(2.125f * lg2a(vk));       // v_t^2.125 (converged)
        Aq = fmaf(-dtm, u, 1.0f);                // 1 - w_t
        Bq = g_t;
    }
    affine_scan(Aq, Bq, lane, warp, shA, shB);
    float q_next = Aq + Bq;                      // q_{t+1} (q_0 = 1)

    // ---- BOLD readout ------------------------------------------------------
    if (active) {
        float yt = fmaf(-YK1, q_next, YC);
        yt = fmaf(-YK3, v_next, yt);
        yt = fmaf(-YK2, q_next * rcpa(v_next), yt);
        y_out[t] = yt;
    }
}

extern "C" void kernel_launch(void* const* d_in, const int* in_sizes, int n_in,
                              void* d_out, int out_size) {
    const float* mtt = (const float*)d_in[0];
    float* y = (float*)d_out;
    bold_pits_kernel<<<1, NT>>>(mtt, y);
}

// round 8
// speedup vs baseline: 8.4074x; 1.2963x over previous
#include <cuda_runtime.h>
#include <cuda_bf16.h>

// Balloon-Windkessel BOLD, 1000 Euler steps — parallel-in-time, v2.
// - (s,f): closed form per step (linear subsystem).
// - v: quasi-static warm start vk = f^alpha, then 3 Newton sweeps, each an
//      affine parallel scan. err ~ err^2 per sweep: 0.05 -> 3e-3 -> 1e-5 -> 2e-10.
// - q: one exact affine scan given converged v.
// - Exclusive result (v_t) extracted via shfl_up of the inclusive scan: no
//   smem shift, no extra barrier. Warp-aggregate arrays double-buffered so
//   each pass needs exactly 2 __syncthreads. 8 barriers total (was ~23).

#define N_STEPS 1000
#define NT      1024
#define DT      0.01f
#define RHO     0.34f
#define ALPHA   0.32f
#define NEWTON_ITERS 3

#define LOG2R   (-0.0071769220f)   // log2(sqrt(1 - h + h^2)), h = 0.01
#define THETA   (0.0087035531f)    // atan2(sqrt(3)/2*h, 1 - h/2)
#define INVSQ3  (0.57735026919f)
#define L66     (-0.5994621118f)   // log2(0.66)

#define YC   0.0972f
#define YK1  0.0476f
#define YK2  0.04f
#define YK3  0.0096f

__device__ __forceinline__ float ex2a(float x){ float r; asm("ex2.approx.f32 %0,%1;":"=f"(r):"f"(x)); return r; }
__device__ __forceinline__ float lg2a(float x){ float r; asm("lg2.approx.f32 %0,%1;":"=f"(r):"f"(x)); return r; }
__device__ __forceinline__ float sina(float x){ float r; asm("sin.approx.f32 %0,%1;":"=f"(r):"f"(x)); return r; }
__device__ __forceinline__ float cosa(float x){ float r; asm("cos.approx.f32 %0,%1;":"=f"(r):"f"(x)); return r; }
__device__ __forceinline__ float rcpa(float x){ float r; asm("rcp.approx.f32 %0,%1;":"=f"(r):"f"(x)); return r; }

// Inclusive+exclusive block scan of affine maps x -> A*x + B.
// On return: (A,B) = inclusive prefix for this thread, (exA,exB) = exclusive.
// Exactly 2 __syncthreads; sA/sB must alternate between calls (double buffer).
__device__ __forceinline__ void affine_scan(float& A, float& B,
                                            float& exA, float& exB,
                                            int lane, int warp,
                                            volatile float* sA, volatile float* sB) {
    #pragma unroll
    for (int d = 1; d < 32; d <<= 1) {
        float pA = __shfl_up_sync(0xffffffffu, A, d);
        float pB = __shfl_up_sync(0xffffffffu, B, d);
        if (lane >= d) { B = fmaf(A, pB, B); A = A * pA; }
    }
    if (lane == 31) { sA[warp] = A; sB[warp] = B; }
    __syncthreads();
    if (warp == 0) {
        float wA = sA[lane], wB = sB[lane];
        #pragma unroll
        for (int d = 1; d < 32; d <<= 1) {
            float pA = __shfl_up_sync(0xffffffffu, wA, d);
            float pB = __shfl_up_sync(0xffffffffu, wB, d);
            if (lane >= d) { wB = fmaf(wA, pB, wB); wA = wA * pA; }
        }
        sA[lane] = wA; sB[lane] = wB;
    }
    __syncthreads();
    float pA = 1.0f, pB = 0.0f;
    if (warp > 0) { pA = sA[warp - 1]; pB = sB[warp - 1]; }
    // full inclusive = local o prefix
    B = fmaf(A, pB, B);
    A = A * pA;
    // exclusive = inclusive of (t-1); lane 0 takes the warp prefix
    exA = __shfl_up_sync(0xffffffffu, A, 1);
    exB = __shfl_up_sync(0xffffffffu, B, 1);
    if (lane == 0) { exA = pA; exB = pB; }
}

__global__ void __launch_bounds__(NT, 1)
bold_pits_kernel(const float* __restrict__ mtt_ptr, float* __restrict__ y_out) {
    __shared__ float sA0[32], sB0[32], sA1[32], sB1[32];

    const int t    = threadIdx.x;
    const int lane = t & 31;
    const int warp = t >> 5;
    const bool active = (t < N_STEPS);

    const float mtt = mtt_ptr[0];
    const float dtm = DT / mtt;

    // ---- elementwise: f_t closed form, E_t, coefficients, warm start ------
    float a_t = 0.0f, g_t = 0.0f, vk = 1.0f;
    if (active) {
        float tf  = (float)t;
        float rp  = ex2a(LOG2R * tf);
        float ang = THETA * tf;
        float f   = 2.0f - rp * fmaf(sina(ang), INVSQ3, cosa(ang));
        float E   = 1.0f - ex2a(L66 * rcpa(f));
        a_t = dtm * f;
        g_t = (dtm / RHO) * f * E;
        vk  = ex2a(ALPHA * lg2a(f));     // quasi-static guess of v_t
    }

    // ---- Newton sweeps for v (each = one affine scan) ---------------------
    float v_next = 1.0f;
    #pragma unroll
    for (int it = 0; it < NEWTON_ITERS; ++it) {
        float A = 1.0f, B = 0.0f, exA, exB;
        if (active) {
            float u = ex2a(2.125f * lg2a(vk));   // vk^2.125
            A = fmaf(-3.125f * dtm, u, 1.0f);
            B = fmaf(2.125f * dtm, vk * u, a_t); // a_t + 2.125*dtm*vk^3.125
        }
        if (it & 1) affine_scan(A, B, exA, exB, lane, warp, sA1, sB1);
        else        affine_scan(A, B, exA, exB, lane, warp, sA0, sB0);
        v_next = A + B;          // v_{t+1} = inclusive applied to v_0 = 1
        vk     = exA + exB;      // v_t     = exclusive applied to v_0 = 1
    }

    // ---- exact affine scan for q (uses converged v_t = vk) ----------------
    float Aq = 1.0f, Bq = 0.0f, exAq, exBq;
    if (active) {
        float u = ex2a(2.125f * lg2a(vk));       // v_t^2.125
        Aq = fmaf(-dtm, u, 1.0f);
        Bq = g_t;
    }
    affine_scan(Aq, Bq, exAq, exBq, lane, warp,
                (NEWTON_ITERS & 1) ? sA1 : sA0,
                (NEWTON_ITERS & 1) ? sB1 : sB0);
    float q_next = Aq + Bq;                      // q_{t+1}

    // ---- BOLD readout ------------------------------------------------------
    if (active) {
        float yt = fmaf(-YK1, q_next, YC);
        yt = fmaf(-YK3, v_next, yt);
        yt = fmaf(-YK2, q_next * rcpa(v_next), yt);
        y_out[t] = yt;
    }
}

extern "C" void kernel_launch(void* const* d_in, const int* in_sizes, int n_in,
                              void* d_out, int out_size) {
    const float* mtt = (const float*)d_in[0];
    float* y = (float*)d_out;
    bold_pits_kernel<<<1, NT>>>(mtt, y);
}